// round 12
// baseline (speedup 1.0000x reference)
#include <cuda_runtime.h>
#include <cuda_fp16.h>
#include <cstdint>

// Problem constants
constexpr int B_  = 2;
constexpr int S_  = 2048;
constexpr int H_  = 2048;
constexpr int NH_ = 16;
constexpr int HD_ = 128;
constexpr float SC_L2E = 0.12751743159532244f;   // (1/sqrt(128)) * log2(e)

// Scratch (static device arrays; allocation APIs are forbidden)
__device__ __half g_hin[3 * (size_t)B_ * S_ * H_];   // fp16 query/key/value
__device__ __half g_hw [4 * (size_t)H_ * H_];        // fp16 Wq/Wk/Wv/Wo
__device__ __half g_hq [(size_t)B_ * S_ * H_];       // q proj (fp16)
__device__ __half g_hk [(size_t)B_ * S_ * H_];       // k proj (fp16)
__device__ __half g_hvt[(size_t)B_ * S_ * H_];       // v proj, [b][h*HD+d][s]
__device__ __half g_hctx[(size_t)B_ * S_ * H_];      // attention output (fp16)

// GEMM tiling: CTA 256x128, k-chunk 64 halves (128B rows), 4-stage cp.async,
// 512 threads = 16 warps (4m x 4n), warp tile 64x32.
constexpr int TM = 256, TN = 128, KC = 64, STAGES = 4;
constexpr int A_BYTES   = TM * 128;
constexpr int B_BYTES   = TN * 128;
constexpr int STG_BYTES = A_BYTES + B_BYTES;             // 49152
constexpr int SMEM_BYTES = STAGES * STG_BYTES;           // 196608

// Flash kernel smem: Q (2 sub-tiles of 128x64h) + 3-stage K,V ring.
constexpr int FT = 16384;                    // one 128x64-half sub-tile
constexpr int OFF_Q  = 0;                    // 2 sub-tiles = 32 KB
constexpr int OFF_KV = 2 * FT;               // 3 stages x (K 2FT + V 2FT)
constexpr int KV_STG = 4 * FT;               // 64 KB per stage
constexpr int FLASH_SMEM = 2 * FT + 3 * KV_STG;          // 229376 B

// ---------------------------------------------------------------------------
__device__ __forceinline__ uint32_t smem_u32(const void* p) {
    uint32_t a;
    asm("{ .reg .u64 t; cvta.to.shared.u64 t, %1; cvt.u32.u64 %0, t; }"
        : "=r"(a) : "l"(p));
    return a;
}
__device__ __forceinline__ void cpa16(uint32_t d, const void* s) {
    asm volatile("cp.async.cg.shared.global [%0], [%1], 16;" :: "r"(d), "l"(s));
}
__device__ __forceinline__ void mma16(float* c, const uint32_t* a,
                                      const uint32_t* b) {
    asm volatile(
        "mma.sync.aligned.m16n8k16.row.col.f32.f16.f16.f32 "
        "{%0,%1,%2,%3},{%4,%5,%6,%7},{%8,%9},{%0,%1,%2,%3};"
        : "+f"(c[0]), "+f"(c[1]), "+f"(c[2]), "+f"(c[3])
        : "r"(a[0]), "r"(a[1]), "r"(a[2]), "r"(a[3]), "r"(b[0]), "r"(b[1]));
}
__device__ __forceinline__ uint32_t packh2(float x, float y) {
    const __half2 h = __floats2half2_rn(x, y);
    return *reinterpret_cast<const uint32_t*>(&h);
}

// fp32 -> fp16: 3 equal-size inputs (query/key/value), one launch.
__global__ __launch_bounds__(256) void f2h3_kernel(
    const float4* __restrict__ x0, const float4* __restrict__ x1,
    const float4* __restrict__ x2, uint2* __restrict__ y, int n4)
{
    const int i = blockIdx.x * 256 + threadIdx.x;
    const float4* src = (blockIdx.y == 0) ? x0 : (blockIdx.y == 1) ? x1 : x2;
    const float4 v = src[i];
    y[(size_t)blockIdx.y * n4 + i] = make_uint2(packh2(v.x, v.y),
                                                packh2(v.z, v.w));
}
// fp32 -> fp16: 4 equal-size weights, one launch.
__global__ __launch_bounds__(256) void f2h4_kernel(
    const float4* __restrict__ x0, const float4* __restrict__ x1,
    const float4* __restrict__ x2, const float4* __restrict__ x3,
    uint2* __restrict__ y, int n4)
{
    const int i = blockIdx.x * 256 + threadIdx.x;
    const float4* src = (blockIdx.y == 0) ? x0 : (blockIdx.y == 1) ? x1
                      : (blockIdx.y == 2) ? x2 : x3;
    const float4 v = src[i];
    y[(size_t)blockIdx.y * n4 + i] = make_uint2(packh2(v.x, v.y),
                                                packh2(v.z, v.w));
}

// ---------------------------------------------------------------------------
// Shared GEMM mainloop (512 threads): acc[4][4][4] = A-tile @ B-tile^T.
// ---------------------------------------------------------------------------
__device__ __forceinline__ void gemm_mainloop(
    const __half* __restrict__ A, int lda,
    const __half* __restrict__ Bm, int ldb,
    char* smc, float acc[4][4][4], int K)
{
    const uint32_t sbase = smem_u32(smc);
    const int tid = threadIdx.x;
    const int lane = tid & 31, wid = tid >> 5;
    const int g = lane >> 2, tg = lane & 3;
    const int wm = (wid >> 2) * 64, wn = (wid & 3) * 32;
    const int r8 = tid >> 3, c8 = tid & 7;         // r8 in 0..63
    const int sc8 = ((c8 ^ (r8 & 7)) << 4);
    const int KIT = K / KC;

    auto stage_load = [&](int s, int kt) {
        const __half* Ak = A + kt * KC;
        const __half* Bk = Bm + kt * KC;
        const uint32_t ab = sbase + (uint32_t)(s * STG_BYTES);
        const uint32_t bb = ab + A_BYTES;
#pragma unroll
        for (int j = 0; j < 4; j++) {
            const int r = r8 + 64 * j;
            cpa16(ab + r * 128 + sc8, Ak + (size_t)r * lda + c8 * 8);
        }
#pragma unroll
        for (int j = 0; j < 2; j++) {
            const int r = r8 + 64 * j;
            cpa16(bb + r * 128 + sc8, Bk + (size_t)r * ldb + c8 * 8);
        }
        asm volatile("cp.async.commit_group;" ::: "memory");
    };

    stage_load(0, 0);
    stage_load(1, 1);
    stage_load(2, 2);

    for (int kt = 0; kt < KIT; kt++) {
        if (kt < KIT - 2) {
            asm volatile("cp.async.wait_group 2;" ::: "memory");
        } else if (kt == KIT - 2) {
            asm volatile("cp.async.wait_group 1;" ::: "memory");
        } else {
            asm volatile("cp.async.wait_group 0;" ::: "memory");
        }
        __syncthreads();
        if (kt + 3 < KIT) stage_load((kt + 3) % STAGES, kt + 3);

        const char* Ab = smc + (kt % STAGES) * STG_BYTES;
        const char* Bb = Ab + A_BYTES;

#pragma unroll
        for (int h = 0; h < 2; h++) {
            const int cb = ((2 * tg + h) ^ g) << 4;
            uint4 va[4][2], vb[4];
#pragma unroll
            for (int mf = 0; mf < 4; mf++) {
                const int rg = wm + mf * 16 + g;
                va[mf][0] = *(const uint4*)(Ab + rg * 128 + cb);
                va[mf][1] = *(const uint4*)(Ab + (rg + 8) * 128 + cb);
            }
#pragma unroll
            for (int nf = 0; nf < 4; nf++)
                vb[nf] = *(const uint4*)(Bb + (wn + nf * 8 + g) * 128 + cb);

#pragma unroll
            for (int s = 0; s < 2; s++) {
                uint32_t af[4][4], bf[4][2];
#pragma unroll
                for (int mf = 0; mf < 4; mf++) {
                    const uint32_t* u0 = (const uint32_t*)&va[mf][0];
                    const uint32_t* u1 = (const uint32_t*)&va[mf][1];
                    af[mf][0] = u0[2 * s];
                    af[mf][1] = u1[2 * s];
                    af[mf][2] = u0[2 * s + 1];
                    af[mf][3] = u1[2 * s + 1];
                }
#pragma unroll
                for (int nf = 0; nf < 4; nf++) {
                    const uint32_t* u = (const uint32_t*)&vb[nf];
                    bf[nf][0] = u[2 * s];
                    bf[nf][1] = u[2 * s + 1];
                }
#pragma unroll
                for (int mf = 0; mf < 4; mf++)
#pragma unroll
                    for (int nf = 0; nf < 4; nf++)
                        mma16(acc[mf][nf], af[mf], bf[nf]);
            }
        }
    }
}

// ---------------------------------------------------------------------------
// Merged Q/K/V projection: blockIdx.z selects input/weight/bias/output.
//   z=0 -> hq (row-major), z=1 -> hk (row-major), z=2 -> hvt (transposed).
// ---------------------------------------------------------------------------
__global__ __launch_bounds__(512, 1) void proj_kernel(
    const __half* __restrict__ hin, const __half* __restrict__ hw,
    __half* __restrict__ hq, __half* __restrict__ hk,
    __half* __restrict__ hvt,
    const float* __restrict__ bq, const float* __restrict__ bk,
    const float* __restrict__ bv)
{
    extern __shared__ char smc[];
    const int z = blockIdx.z;
    const size_t NIN = (size_t)B_ * S_ * H_;
    const size_t NW  = (size_t)H_ * H_;
    const int m0 = blockIdx.y * TM, n0 = blockIdx.x * TN;

    const __half* A  = hin + z * NIN + (size_t)m0 * H_;
    const __half* Bm = hw + z * NW + (size_t)n0 * H_;
    const float* bias = (z == 0) ? bq : (z == 1) ? bk : bv;

    float acc[4][4][4];
#pragma unroll
    for (int i = 0; i < 4; i++)
#pragma unroll
        for (int j = 0; j < 4; j++)
#pragma unroll
            for (int l = 0; l < 4; l++) acc[i][j][l] = 0.0f;

    gemm_mainloop(A, H_, Bm, H_, smc, acc, H_);

    const int lane = threadIdx.x & 31, wid = threadIdx.x >> 5;
    const int g = lane >> 2, tg = lane & 3;
    const int wm = (wid >> 2) * 64, wn = (wid & 3) * 32;
    __half* Crow = (z == 0) ? hq : hk;

#pragma unroll
    for (int mf = 0; mf < 4; mf++) {
#pragma unroll
        for (int hf = 0; hf < 2; hf++) {
            const int mg = m0 + wm + mf * 16 + g + hf * 8;
#pragma unroll
            for (int nf = 0; nf < 4; nf++) {
                const int cl = wn + nf * 8 + 2 * tg;
                const float v0 = acc[mf][nf][hf * 2 + 0] + bias[n0 + cl];
                const float v1 = acc[mf][nf][hf * 2 + 1] + bias[n0 + cl + 1];
                if (z == 2) {
                    const int b = mg >> 11, s = mg & (S_ - 1);
                    hvt[(size_t)b * H_ * S_ + (size_t)(n0 + cl) * S_ + s] =
                        __float2half_rn(v0);
                    hvt[(size_t)b * H_ * S_ + (size_t)(n0 + cl + 1) * S_ + s] =
                        __float2half_rn(v1);
                } else {
                    *reinterpret_cast<uint32_t*>(
                        Crow + (size_t)mg * H_ + n0 + cl) = packh2(v0, v1);
                }
            }
        }
    }
}

// Final output GEMM: out = hctx @ Wo^T + bo (fp32 store).
__global__ __launch_bounds__(512, 1) void out_kernel(
    const __half* __restrict__ hctx, const __half* __restrict__ hwo,
    float* __restrict__ out, const float* __restrict__ bo)
{
    extern __shared__ char smc[];
    const int m0 = blockIdx.y * TM, n0 = blockIdx.x * TN;
    const __half* A  = hctx + (size_t)m0 * H_;
    const __half* Bm = hwo + (size_t)n0 * H_;

    float acc[4][4][4];
#pragma unroll
    for (int i = 0; i < 4; i++)
#pragma unroll
        for (int j = 0; j < 4; j++)
#pragma unroll
            for (int l = 0; l < 4; l++) acc[i][j][l] = 0.0f;

    gemm_mainloop(A, H_, Bm, H_, smc, acc, H_);

    const int lane = threadIdx.x & 31, wid = threadIdx.x >> 5;
    const int g = lane >> 2, tg = lane & 3;
    const int wm = (wid >> 2) * 64, wn = (wid & 3) * 32;

#pragma unroll
    for (int mf = 0; mf < 4; mf++) {
#pragma unroll
        for (int hf = 0; hf < 2; hf++) {
            const int mg = m0 + wm + mf * 16 + g + hf * 8;
#pragma unroll
            for (int nf = 0; nf < 4; nf++) {
                const int cl = wn + nf * 8 + 2 * tg;
                const float v0 = acc[mf][nf][hf * 2 + 0] + bo[n0 + cl];
                const float v1 = acc[mf][nf][hf * 2 + 1] + bo[n0 + cl + 1];
                *reinterpret_cast<float2*>(
                    out + (size_t)mg * H_ + n0 + cl) = make_float2(v0, v1);
            }
        }
    }
}

// ---------------------------------------------------------------------------
// Fused flash attention (unchanged from R11): per CTA = (b, h, 128-q-tile).
// ---------------------------------------------------------------------------
__global__ __launch_bounds__(256, 1) void flash_attn(
    const __half* __restrict__ hq, const __half* __restrict__ hk,
    const __half* __restrict__ hvt, __half* __restrict__ hctx)
{
    extern __shared__ char smc[];
    const uint32_t sb = smem_u32(smc);
    const int tid = threadIdx.x, lane = tid & 31, w = tid >> 5;
    const int g = lane >> 2, tg = lane & 3;
    const int zh = blockIdx.y, zb = blockIdx.z;
    const int q0 = blockIdx.x * 128;
    const size_t sSH = (size_t)S_ * H_;

    const __half* Qg = hq + zb * sSH + (size_t)q0 * H_ + zh * HD_;
    const __half* Kg = hk + zb * sSH + zh * HD_;
    const __half* Vg = hvt + zb * sSH + (size_t)(zh * HD_) * S_;  // rows=d

    const int r8 = tid >> 3, c8 = tid & 7;

    auto stage = [&](uint32_t dst, const __half* gp, int stride) {
#pragma unroll
        for (int j = 0; j < 4; j++) {
            const int r = r8 + 32 * j;
            cpa16(sb + dst + r * 128 + ((c8 ^ (r & 7)) << 4),
                  gp + (size_t)r * stride + c8 * 8);
        }
    };
    auto load_kv = [&](int j) {
        const __half* kp = Kg + (size_t)(j * 128) * H_;
        const __half* vp = Vg + j * 128;
        const uint32_t kd = OFF_KV + (j % 3) * KV_STG;
        const uint32_t vd = kd + 2 * FT;
        stage(kd, kp, H_);      stage(kd + FT, kp + 64, H_);
        stage(vd, vp, S_);      stage(vd + FT, vp + 64, S_);
        asm volatile("cp.async.commit_group;" ::: "memory");
    };

    // Prologue: group0 = Q + KV0, group1 = KV1.
    stage(OFF_Q, Qg, H_);
    stage(OFF_Q + FT, Qg + 64, H_);
    {
        stage(OFF_KV, Kg, H_);
        stage(OFF_KV + FT, Kg + 64, H_);
        stage(OFF_KV + 2 * FT, Vg, S_);
        stage(OFF_KV + 3 * FT, Vg + 64, S_);
        asm volatile("cp.async.commit_group;" ::: "memory");
    }
    load_kv(1);

    float ctxa[16][4];
#pragma unroll
    for (int i = 0; i < 16; i++)
#pragma unroll
        for (int l = 0; l < 4; l++) ctxa[i][l] = 0.0f;
    float rs0 = 0.f, rs1 = 0.f;
    uint4 qv[2][2][2];           // [sub-tile][h-slice][row g / g+8]

    const int lq = lane >> 3, lrt = lane & 7;
    const int lrow_off = (8 * (lq >> 1) + lrt) * 128;
    const int lpar = lq & 1;

    for (int j = 0; j < 16; j++) {
        if (j < 15) {
            asm volatile("cp.async.wait_group 1;" ::: "memory");
        } else {
            asm volatile("cp.async.wait_group 0;" ::: "memory");
        }
        __syncthreads();
        if (j + 2 < 16) load_kv(j + 2);

        const char* Kb = smc + OFF_KV + (j % 3) * KV_STG;
        const uint32_t Vb = sb + OFF_KV + (j % 3) * KV_STG + 2 * FT;

        if (j == 0) {
            const char* Qb = smc + OFF_Q;
#pragma unroll
            for (int st = 0; st < 2; st++)
#pragma unroll
                for (int h = 0; h < 2; h++) {
                    const int cb = ((2 * tg + h) ^ g) << 4;
                    const int rg = w * 16 + g;
                    qv[st][h][0] = *(const uint4*)(Qb + st * FT + rg * 128 + cb);
                    qv[st][h][1] = *(const uint4*)(Qb + st * FT + (rg + 8) * 128 + cb);
                }
        }

        float sacc[16][4];
#pragma unroll
        for (int i = 0; i < 16; i++)
#pragma unroll
            for (int l = 0; l < 4; l++) sacc[i][l] = 0.0f;

#pragma unroll
        for (int st = 0; st < 2; st++)
#pragma unroll
            for (int h = 0; h < 2; h++) {
                const int cb = ((2 * tg + h) ^ g) << 4;
                const char* Kst = Kb + st * FT;
                uint32_t af[2][4];
                {
                    const uint32_t* u0 = (const uint32_t*)&qv[st][h][0];
                    const uint32_t* u1 = (const uint32_t*)&qv[st][h][1];
#pragma unroll
                    for (int s = 0; s < 2; s++) {
                        af[s][0] = u0[2 * s];
                        af[s][1] = u1[2 * s];
                        af[s][2] = u0[2 * s + 1];
                        af[s][3] = u1[2 * s + 1];
                    }
                }
#pragma unroll
                for (int half = 0; half < 2; half++) {
                    uint4 vb[8];
#pragma unroll
                    for (int nb = 0; nb < 8; nb++)
                        vb[nb] = *(const uint4*)(
                            Kst + (64 * half + 8 * nb + g) * 128 + cb);
#pragma unroll
                    for (int s = 0; s < 2; s++)
#pragma unroll
                        for (int nb = 0; nb < 8; nb++) {
                            const uint32_t* u = (const uint32_t*)&vb[nb];
                            uint32_t bf[2] = {u[2 * s], u[2 * s + 1]};
                            mma16(sacc[8 * half + nb], af[s], bf);
                        }
                }
            }

        uint32_t P[8][4];
#pragma unroll
        for (int c = 0; c < 8; c++) {
            float e0 = exp2f(sacc[2 * c][0] * SC_L2E);
            float e1 = exp2f(sacc[2 * c][1] * SC_L2E);
            float e2 = exp2f(sacc[2 * c][2] * SC_L2E);
            float e3 = exp2f(sacc[2 * c][3] * SC_L2E);
            float f0 = exp2f(sacc[2 * c + 1][0] * SC_L2E);
            float f1 = exp2f(sacc[2 * c + 1][1] * SC_L2E);
            float f2 = exp2f(sacc[2 * c + 1][2] * SC_L2E);
            float f3 = exp2f(sacc[2 * c + 1][3] * SC_L2E);
            rs0 += (e0 + e1) + (f0 + f1);
            rs1 += (e2 + e3) + (f2 + f3);
            P[c][0] = packh2(e0, e1);
            P[c][1] = packh2(e2, e3);
            P[c][2] = packh2(f0, f1);
            P[c][3] = packh2(f2, f3);
        }

#pragma unroll
        for (int c = 0; c < 8; c++) {
            const uint32_t Vst = Vb + (c >> 2) * FT;
            const int kc = c & 3;
            const int chv = ((2 * kc + lpar) ^ lrt) << 4;
#pragma unroll
            for (int np = 0; np < 8; np++) {
                const uint32_t addr = Vst + np * 16 * 128 + lrow_off + chv;
                uint32_t b0, b1, b2, b3;
                asm volatile(
                    "ldmatrix.sync.aligned.m8n8.x4.shared.b16 {%0,%1,%2,%3}, [%4];"
                    : "=r"(b0), "=r"(b1), "=r"(b2), "=r"(b3) : "r"(addr));
                uint32_t bfa[2] = {b0, b1}, bfb[2] = {b2, b3};
                mma16(ctxa[2 * np], P[c], bfa);
                mma16(ctxa[2 * np + 1], P[c], bfb);
            }
        }
    }

#pragma unroll
    for (int off = 1; off < 4; off <<= 1) {
        rs0 += __shfl_xor_sync(0xffffffffu, rs0, off);
        rs1 += __shfl_xor_sync(0xffffffffu, rs1, off);
    }
    const float inv0 = 1.0f / rs0, inv1 = 1.0f / rs1;

    const int row0 = q0 + w * 16 + g;
    __half* Cp = hctx + zb * sSH + zh * HD_;
#pragma unroll
    for (int nf = 0; nf < 16; nf++) {
        const int col = nf * 8 + 2 * tg;
        *reinterpret_cast<uint32_t*>(Cp + (size_t)row0 * H_ + col) =
            packh2(ctxa[nf][0] * inv0, ctxa[nf][1] * inv0);
        *reinterpret_cast<uint32_t*>(Cp + (size_t)(row0 + 8) * H_ + col) =
            packh2(ctxa[nf][2] * inv1, ctxa[nf][3] * inv1);
    }
}

// ---------------------------------------------------------------------------
extern "C" void kernel_launch(void* const* d_in, const int* in_sizes, int n_in,
                              void* d_out, int out_size)
{
    const float* query = (const float*)d_in[0];
    const float* key_  = (const float*)d_in[1];
    const float* value = (const float*)d_in[2];
    const float* Wq = (const float*)d_in[3];
    const float* bq = (const float*)d_in[4];
    const float* Wk = (const float*)d_in[5];
    const float* bk = (const float*)d_in[6];
    const float* Wv = (const float*)d_in[7];
    const float* bv = (const float*)d_in[8];
    const float* Wo = (const float*)d_in[9];
    const float* bo = (const float*)d_in[10];
    float* out = (float*)d_out;

    __half *hin, *hw, *hq, *hk, *hvt, *hctx;
    cudaGetSymbolAddress((void**)&hin,  g_hin);
    cudaGetSymbolAddress((void**)&hw,   g_hw);
    cudaGetSymbolAddress((void**)&hq,   g_hq);
    cudaGetSymbolAddress((void**)&hk,   g_hk);
    cudaGetSymbolAddress((void**)&hvt,  g_hvt);
    cudaGetSymbolAddress((void**)&hctx, g_hctx);

    const size_t NIN = (size_t)B_ * S_ * H_;
    const size_t NW  = (size_t)H_ * H_;

    // fp32 -> fp16 conversions: 2 merged launches.
    f2h3_kernel<<<dim3((int)(NIN / 4 / 256), 3), 256>>>(
        (const float4*)query, (const float4*)key_, (const float4*)value,
        (uint2*)hin, (int)(NIN / 4));
    f2h4_kernel<<<dim3((int)(NW / 4 / 256), 4), 256>>>(
        (const float4*)Wq, (const float4*)Wk, (const float4*)Wv,
        (const float4*)Wo, (uint2*)hw, (int)(NW / 4));

    cudaFuncSetAttribute(proj_kernel,
                         cudaFuncAttributeMaxDynamicSharedMemorySize, SMEM_BYTES);
    cudaFuncSetAttribute(out_kernel,
                         cudaFuncAttributeMaxDynamicSharedMemorySize, SMEM_BYTES);
    cudaFuncSetAttribute(flash_attn,
                         cudaFuncAttributeMaxDynamicSharedMemorySize, FLASH_SMEM);

    const dim3 gproj(H_ / TN, (B_ * S_) / TM, 3);   // (16, 16, 3)
    const dim3 gout(H_ / TN, (B_ * S_) / TM, 1);    // (16, 16)
    const dim3 gfa(S_ / 128, NH_, B_);              // (16, 16, 2)

    // Q/K/V projections in one launch (bias fused; V stored transposed).
    proj_kernel<<<gproj, 512, SMEM_BYTES>>>(hin, hw, hq, hk, hvt, bq, bk, bv);

    flash_attn<<<gfa, 256, FLASH_SMEM>>>(hq, hk, hvt, hctx);

    out_kernel<<<gout, 512, SMEM_BYTES>>>(hctx, hw + 3 * NW, out, bo);
}

// round 13
// speedup vs baseline: 1.0578x; 1.0578x over previous
#include <cuda_runtime.h>
#include <cuda_fp16.h>
#include <cstdint>

// Problem constants
constexpr int B_  = 2;
constexpr int S_  = 2048;
constexpr int H_  = 2048;
constexpr int NH_ = 16;
constexpr int HD_ = 128;
constexpr float SC_L2E = 0.12751743159532244f;   // (1/sqrt(128)) * log2(e)

// Scratch (static device arrays; allocation APIs are forbidden)
__device__ __half g_hin[3 * (size_t)B_ * S_ * H_];   // fp16 query/key/value
__device__ __half g_hw [4 * (size_t)H_ * H_];        // fp16 Wq/Wk/Wv/Wo
__device__ __half g_hq [(size_t)B_ * S_ * H_];       // q proj (fp16)
__device__ __half g_hk [(size_t)B_ * S_ * H_];       // k proj (fp16)
__device__ __half g_hvt[(size_t)B_ * S_ * H_];       // v proj, [b][h*HD+d][s]
__device__ __half g_hctx[(size_t)B_ * S_ * H_];      // attention output (fp16)

// GEMM tiling: CTA 128x128, k-chunk 64 halves (128B rows), 3-stage cp.async,
// 256 threads = 8 warps (2m x 4n), warp tile 64x32, 2 CTAs/SM.
constexpr int TM = 128, TN = 128, KC = 64, STAGES = 3;
constexpr int A_BYTES   = TM * 128;                      // 16384
constexpr int B_BYTES   = TN * 128;                      // 16384
constexpr int STG_BYTES = A_BYTES + B_BYTES;             // 32768
constexpr int SMEM_BYTES = STAGES * STG_BYTES;           // 98304 (x2 CTA = 192K)

// Flash kernel smem: Q (2 sub-tiles of 128x64h) + 3-stage K,V ring.
constexpr int FT = 16384;                    // one 128x64-half sub-tile
constexpr int OFF_Q  = 0;                    // 2 sub-tiles = 32 KB
constexpr int OFF_KV = 2 * FT;               // 3 stages x (K 2FT + V 2FT)
constexpr int KV_STG = 4 * FT;               // 64 KB per stage
constexpr int FLASH_SMEM = 2 * FT + 3 * KV_STG;          // 229376 B

// ---------------------------------------------------------------------------
__device__ __forceinline__ uint32_t smem_u32(const void* p) {
    uint32_t a;
    asm("{ .reg .u64 t; cvta.to.shared.u64 t, %1; cvt.u32.u64 %0, t; }"
        : "=r"(a) : "l"(p));
    return a;
}
__device__ __forceinline__ void cpa16(uint32_t d, const void* s) {
    asm volatile("cp.async.cg.shared.global [%0], [%1], 16;" :: "r"(d), "l"(s));
}
__device__ __forceinline__ void mma16(float* c, const uint32_t* a,
                                      const uint32_t* b) {
    asm volatile(
        "mma.sync.aligned.m16n8k16.row.col.f32.f16.f16.f32 "
        "{%0,%1,%2,%3},{%4,%5,%6,%7},{%8,%9},{%0,%1,%2,%3};"
        : "+f"(c[0]), "+f"(c[1]), "+f"(c[2]), "+f"(c[3])
        : "r"(a[0]), "r"(a[1]), "r"(a[2]), "r"(a[3]), "r"(b[0]), "r"(b[1]));
}
__device__ __forceinline__ uint32_t packh2(float x, float y) {
    const __half2 h = __floats2half2_rn(x, y);
    return *reinterpret_cast<const uint32_t*>(&h);
}

// fp32 -> fp16: 3 equal-size inputs (query/key/value), one launch.
__global__ __launch_bounds__(256) void f2h3_kernel(
    const float4* __restrict__ x0, const float4* __restrict__ x1,
    const float4* __restrict__ x2, uint2* __restrict__ y, int n4)
{
    const int i = blockIdx.x * 256 + threadIdx.x;
    const float4* src = (blockIdx.y == 0) ? x0 : (blockIdx.y == 1) ? x1 : x2;
    const float4 v = src[i];
    y[(size_t)blockIdx.y * n4 + i] = make_uint2(packh2(v.x, v.y),
                                                packh2(v.z, v.w));
}
// fp32 -> fp16: 4 equal-size weights, one launch.
__global__ __launch_bounds__(256) void f2h4_kernel(
    const float4* __restrict__ x0, const float4* __restrict__ x1,
    const float4* __restrict__ x2, const float4* __restrict__ x3,
    uint2* __restrict__ y, int n4)
{
    const int i = blockIdx.x * 256 + threadIdx.x;
    const float4* src = (blockIdx.y == 0) ? x0 : (blockIdx.y == 1) ? x1
                      : (blockIdx.y == 2) ? x2 : x3;
    const float4 v = src[i];
    y[(size_t)blockIdx.y * n4 + i] = make_uint2(packh2(v.x, v.y),
                                                packh2(v.z, v.w));
}

// ---------------------------------------------------------------------------
// Shared GEMM mainloop (256 threads, 128x128 tile): acc = A-tile @ B-tile^T.
// 8 warps as 2(m) x 4(n); warp tile 64x32.
// ---------------------------------------------------------------------------
__device__ __forceinline__ void gemm_mainloop(
    const __half* __restrict__ A, int lda,
    const __half* __restrict__ Bm, int ldb,
    char* smc, float acc[4][4][4], int K)
{
    const uint32_t sbase = smem_u32(smc);
    const int tid = threadIdx.x;
    const int lane = tid & 31, wid = tid >> 5;
    const int g = lane >> 2, tg = lane & 3;
    const int wm = (wid >> 2) * 64, wn = (wid & 3) * 32;
    const int r8 = tid >> 3, c8 = tid & 7;         // r8 in 0..31
    const int sc8 = ((c8 ^ (r8 & 7)) << 4);
    const int KIT = K / KC;

    auto stage_load = [&](int s, int kt) {
        const __half* Ak = A + kt * KC;
        const __half* Bk = Bm + kt * KC;
        const uint32_t ab = sbase + (uint32_t)(s * STG_BYTES);
        const uint32_t bb = ab + A_BYTES;
#pragma unroll
        for (int j = 0; j < 4; j++) {
            const int r = r8 + 32 * j;
            cpa16(ab + r * 128 + sc8, Ak + (size_t)r * lda + c8 * 8);
        }
#pragma unroll
        for (int j = 0; j < 4; j++) {
            const int r = r8 + 32 * j;
            cpa16(bb + r * 128 + sc8, Bk + (size_t)r * ldb + c8 * 8);
        }
        asm volatile("cp.async.commit_group;" ::: "memory");
    };

    stage_load(0, 0);
    stage_load(1, 1);

    for (int kt = 0; kt < KIT; kt++) {
        if (kt + 1 < KIT) {
            asm volatile("cp.async.wait_group 1;" ::: "memory");
        } else {
            asm volatile("cp.async.wait_group 0;" ::: "memory");
        }
        // Single barrier: publishes kt AND retires kt-1's readers, so
        // stage (kt+2)%3 == (kt-1)%3 is safe to refill below.
        __syncthreads();
        if (kt + 2 < KIT) stage_load((kt + 2) % STAGES, kt + 2);

        const char* Ab = smc + (kt % STAGES) * STG_BYTES;
        const char* Bb = Ab + A_BYTES;

#pragma unroll
        for (int h = 0; h < 2; h++) {
            const int cb = ((2 * tg + h) ^ g) << 4;
            uint4 va[4][2], vb[4];
#pragma unroll
            for (int mf = 0; mf < 4; mf++) {
                const int rg = wm + mf * 16 + g;
                va[mf][0] = *(const uint4*)(Ab + rg * 128 + cb);
                va[mf][1] = *(const uint4*)(Ab + (rg + 8) * 128 + cb);
            }
#pragma unroll
            for (int nf = 0; nf < 4; nf++)
                vb[nf] = *(const uint4*)(Bb + (wn + nf * 8 + g) * 128 + cb);

#pragma unroll
            for (int s = 0; s < 2; s++) {
                uint32_t af[4][4], bf[4][2];
#pragma unroll
                for (int mf = 0; mf < 4; mf++) {
                    const uint32_t* u0 = (const uint32_t*)&va[mf][0];
                    const uint32_t* u1 = (const uint32_t*)&va[mf][1];
                    af[mf][0] = u0[2 * s];
                    af[mf][1] = u1[2 * s];
                    af[mf][2] = u0[2 * s + 1];
                    af[mf][3] = u1[2 * s + 1];
                }
#pragma unroll
                for (int nf = 0; nf < 4; nf++) {
                    const uint32_t* u = (const uint32_t*)&vb[nf];
                    bf[nf][0] = u[2 * s];
                    bf[nf][1] = u[2 * s + 1];
                }
#pragma unroll
                for (int mf = 0; mf < 4; mf++)
#pragma unroll
                    for (int nf = 0; nf < 4; nf++)
                        mma16(acc[mf][nf], af[mf], bf[nf]);
            }
        }
    }
}

// ---------------------------------------------------------------------------
// Merged Q/K/V projection: blockIdx.z selects input/weight/bias/output.
//   z=0 -> hq (row-major), z=1 -> hk (row-major), z=2 -> hvt (transposed).
// ---------------------------------------------------------------------------
__global__ __launch_bounds__(256, 2) void proj_kernel(
    const __half* __restrict__ hin, const __half* __restrict__ hw,
    __half* __restrict__ hq, __half* __restrict__ hk,
    __half* __restrict__ hvt,
    const float* __restrict__ bq, const float* __restrict__ bk,
    const float* __restrict__ bv)
{
    extern __shared__ char smc[];
    const int z = blockIdx.z;
    const size_t NIN = (size_t)B_ * S_ * H_;
    const size_t NW  = (size_t)H_ * H_;
    const int m0 = blockIdx.y * TM, n0 = blockIdx.x * TN;

    const __half* A  = hin + z * NIN + (size_t)m0 * H_;
    const __half* Bm = hw + z * NW + (size_t)n0 * H_;
    const float* bias = (z == 0) ? bq : (z == 1) ? bk : bv;

    float acc[4][4][4];
#pragma unroll
    for (int i = 0; i < 4; i++)
#pragma unroll
        for (int j = 0; j < 4; j++)
#pragma unroll
            for (int l = 0; l < 4; l++) acc[i][j][l] = 0.0f;

    gemm_mainloop(A, H_, Bm, H_, smc, acc, H_);

    const int lane = threadIdx.x & 31, wid = threadIdx.x >> 5;
    const int g = lane >> 2, tg = lane & 3;
    const int wm = (wid >> 2) * 64, wn = (wid & 3) * 32;
    __half* Crow = (z == 0) ? hq : hk;

#pragma unroll
    for (int mf = 0; mf < 4; mf++) {
#pragma unroll
        for (int hf = 0; hf < 2; hf++) {
            const int mg = m0 + wm + mf * 16 + g + hf * 8;
#pragma unroll
            for (int nf = 0; nf < 4; nf++) {
                const int cl = wn + nf * 8 + 2 * tg;
                const float v0 = acc[mf][nf][hf * 2 + 0] + bias[n0 + cl];
                const float v1 = acc[mf][nf][hf * 2 + 1] + bias[n0 + cl + 1];
                if (z == 2) {
                    const int b = mg >> 11, s = mg & (S_ - 1);
                    hvt[(size_t)b * H_ * S_ + (size_t)(n0 + cl) * S_ + s] =
                        __float2half_rn(v0);
                    hvt[(size_t)b * H_ * S_ + (size_t)(n0 + cl + 1) * S_ + s] =
                        __float2half_rn(v1);
                } else {
                    *reinterpret_cast<uint32_t*>(
                        Crow + (size_t)mg * H_ + n0 + cl) = packh2(v0, v1);
                }
            }
        }
    }
}

// Final output GEMM: out = hctx @ Wo^T + bo (fp32 store).
__global__ __launch_bounds__(256, 2) void out_kernel(
    const __half* __restrict__ hctx, const __half* __restrict__ hwo,
    float* __restrict__ out, const float* __restrict__ bo)
{
    extern __shared__ char smc[];
    const int m0 = blockIdx.y * TM, n0 = blockIdx.x * TN;
    const __half* A  = hctx + (size_t)m0 * H_;
    const __half* Bm = hwo + (size_t)n0 * H_;

    float acc[4][4][4];
#pragma unroll
    for (int i = 0; i < 4; i++)
#pragma unroll
        for (int j = 0; j < 4; j++)
#pragma unroll
            for (int l = 0; l < 4; l++) acc[i][j][l] = 0.0f;

    gemm_mainloop(A, H_, Bm, H_, smc, acc, H_);

    const int lane = threadIdx.x & 31, wid = threadIdx.x >> 5;
    const int g = lane >> 2, tg = lane & 3;
    const int wm = (wid >> 2) * 64, wn = (wid & 3) * 32;

#pragma unroll
    for (int mf = 0; mf < 4; mf++) {
#pragma unroll
        for (int hf = 0; hf < 2; hf++) {
            const int mg = m0 + wm + mf * 16 + g + hf * 8;
#pragma unroll
            for (int nf = 0; nf < 4; nf++) {
                const int cl = wn + nf * 8 + 2 * tg;
                const float v0 = acc[mf][nf][hf * 2 + 0] + bo[n0 + cl];
                const float v1 = acc[mf][nf][hf * 2 + 1] + bo[n0 + cl + 1];
                *reinterpret_cast<float2*>(
                    out + (size_t)mg * H_ + n0 + cl) = make_float2(v0, v1);
            }
        }
    }
}

// ---------------------------------------------------------------------------
// Fused flash attention (unchanged): per CTA = (b, h, 128-q-tile).
// ---------------------------------------------------------------------------
__global__ __launch_bounds__(256, 1) void flash_attn(
    const __half* __restrict__ hq, const __half* __restrict__ hk,
    const __half* __restrict__ hvt, __half* __restrict__ hctx)
{
    extern __shared__ char smc[];
    const uint32_t sb = smem_u32(smc);
    const int tid = threadIdx.x, lane = tid & 31, w = tid >> 5;
    const int g = lane >> 2, tg = lane & 3;
    const int zh = blockIdx.y, zb = blockIdx.z;
    const int q0 = blockIdx.x * 128;
    const size_t sSH = (size_t)S_ * H_;

    const __half* Qg = hq + zb * sSH + (size_t)q0 * H_ + zh * HD_;
    const __half* Kg = hk + zb * sSH + zh * HD_;
    const __half* Vg = hvt + zb * sSH + (size_t)(zh * HD_) * S_;  // rows=d

    const int r8 = tid >> 3, c8 = tid & 7;

    auto stage = [&](uint32_t dst, const __half* gp, int stride) {
#pragma unroll
        for (int j = 0; j < 4; j++) {
            const int r = r8 + 32 * j;
            cpa16(sb + dst + r * 128 + ((c8 ^ (r & 7)) << 4),
                  gp + (size_t)r * stride + c8 * 8);
        }
    };
    auto load_kv = [&](int j) {
        const __half* kp = Kg + (size_t)(j * 128) * H_;
        const __half* vp = Vg + j * 128;
        const uint32_t kd = OFF_KV + (j % 3) * KV_STG;
        const uint32_t vd = kd + 2 * FT;
        stage(kd, kp, H_);      stage(kd + FT, kp + 64, H_);
        stage(vd, vp, S_);      stage(vd + FT, vp + 64, S_);
        asm volatile("cp.async.commit_group;" ::: "memory");
    };

    // Prologue: group0 = Q + KV0, group1 = KV1.
    stage(OFF_Q, Qg, H_);
    stage(OFF_Q + FT, Qg + 64, H_);
    {
        stage(OFF_KV, Kg, H_);
        stage(OFF_KV + FT, Kg + 64, H_);
        stage(OFF_KV + 2 * FT, Vg, S_);
        stage(OFF_KV + 3 * FT, Vg + 64, S_);
        asm volatile("cp.async.commit_group;" ::: "memory");
    }
    load_kv(1);

    float ctxa[16][4];
#pragma unroll
    for (int i = 0; i < 16; i++)
#pragma unroll
        for (int l = 0; l < 4; l++) ctxa[i][l] = 0.0f;
    float rs0 = 0.f, rs1 = 0.f;
    uint4 qv[2][2][2];           // [sub-tile][h-slice][row g / g+8]

    const int lq = lane >> 3, lrt = lane & 7;
    const int lrow_off = (8 * (lq >> 1) + lrt) * 128;
    const int lpar = lq & 1;

    for (int j = 0; j < 16; j++) {
        if (j < 15) {
            asm volatile("cp.async.wait_group 1;" ::: "memory");
        } else {
            asm volatile("cp.async.wait_group 0;" ::: "memory");
        }
        __syncthreads();
        if (j + 2 < 16) load_kv(j + 2);

        const char* Kb = smc + OFF_KV + (j % 3) * KV_STG;
        const uint32_t Vb = sb + OFF_KV + (j % 3) * KV_STG + 2 * FT;

        if (j == 0) {
            const char* Qb = smc + OFF_Q;
#pragma unroll
            for (int st = 0; st < 2; st++)
#pragma unroll
                for (int h = 0; h < 2; h++) {
                    const int cb = ((2 * tg + h) ^ g) << 4;
                    const int rg = w * 16 + g;
                    qv[st][h][0] = *(const uint4*)(Qb + st * FT + rg * 128 + cb);
                    qv[st][h][1] = *(const uint4*)(Qb + st * FT + (rg + 8) * 128 + cb);
                }
        }

        float sacc[16][4];
#pragma unroll
        for (int i = 0; i < 16; i++)
#pragma unroll
            for (int l = 0; l < 4; l++) sacc[i][l] = 0.0f;

#pragma unroll
        for (int st = 0; st < 2; st++)
#pragma unroll
            for (int h = 0; h < 2; h++) {
                const int cb = ((2 * tg + h) ^ g) << 4;
                const char* Kst = Kb + st * FT;
                uint32_t af[2][4];
                {
                    const uint32_t* u0 = (const uint32_t*)&qv[st][h][0];
                    const uint32_t* u1 = (const uint32_t*)&qv[st][h][1];
#pragma unroll
                    for (int s = 0; s < 2; s++) {
                        af[s][0] = u0[2 * s];
                        af[s][1] = u1[2 * s];
                        af[s][2] = u0[2 * s + 1];
                        af[s][3] = u1[2 * s + 1];
                    }
                }
#pragma unroll
                for (int half = 0; half < 2; half++) {
                    uint4 vb[8];
#pragma unroll
                    for (int nb = 0; nb < 8; nb++)
                        vb[nb] = *(const uint4*)(
                            Kst + (64 * half + 8 * nb + g) * 128 + cb);
#pragma unroll
                    for (int s = 0; s < 2; s++)
#pragma unroll
                        for (int nb = 0; nb < 8; nb++) {
                            const uint32_t* u = (const uint32_t*)&vb[nb];
                            uint32_t bf[2] = {u[2 * s], u[2 * s + 1]};
                            mma16(sacc[8 * half + nb], af[s], bf);
                        }
                }
            }

        uint32_t P[8][4];
#pragma unroll
        for (int c = 0; c < 8; c++) {
            float e0 = exp2f(sacc[2 * c][0] * SC_L2E);
            float e1 = exp2f(sacc[2 * c][1] * SC_L2E);
            float e2 = exp2f(sacc[2 * c][2] * SC_L2E);
            float e3 = exp2f(sacc[2 * c][3] * SC_L2E);
            float f0 = exp2f(sacc[2 * c + 1][0] * SC_L2E);
            float f1 = exp2f(sacc[2 * c + 1][1] * SC_L2E);
            float f2 = exp2f(sacc[2 * c + 1][2] * SC_L2E);
            float f3 = exp2f(sacc[2 * c + 1][3] * SC_L2E);
            rs0 += (e0 + e1) + (f0 + f1);
            rs1 += (e2 + e3) + (f2 + f3);
            P[c][0] = packh2(e0, e1);
            P[c][1] = packh2(e2, e3);
            P[c][2] = packh2(f0, f1);
            P[c][3] = packh2(f2, f3);
        }

#pragma unroll
        for (int c = 0; c < 8; c++) {
            const uint32_t Vst = Vb + (c >> 2) * FT;
            const int kc = c & 3;
            const int chv = ((2 * kc + lpar) ^ lrt) << 4;
#pragma unroll
            for (int np = 0; np < 8; np++) {
                const uint32_t addr = Vst + np * 16 * 128 + lrow_off + chv;
                uint32_t b0, b1, b2, b3;
                asm volatile(
                    "ldmatrix.sync.aligned.m8n8.x4.shared.b16 {%0,%1,%2,%3}, [%4];"
                    : "=r"(b0), "=r"(b1), "=r"(b2), "=r"(b3) : "r"(addr));
                uint32_t bfa[2] = {b0, b1}, bfb[2] = {b2, b3};
                mma16(ctxa[2 * np], P[c], bfa);
                mma16(ctxa[2 * np + 1], P[c], bfb);
            }
        }
    }

#pragma unroll
    for (int off = 1; off < 4; off <<= 1) {
        rs0 += __shfl_xor_sync(0xffffffffu, rs0, off);
        rs1 += __shfl_xor_sync(0xffffffffu, rs1, off);
    }
    const float inv0 = 1.0f / rs0, inv1 = 1.0f / rs1;

    const int row0 = q0 + w * 16 + g;
    __half* Cp = hctx + zb * sSH + zh * HD_;
#pragma unroll
    for (int nf = 0; nf < 16; nf++) {
        const int col = nf * 8 + 2 * tg;
        *reinterpret_cast<uint32_t*>(Cp + (size_t)row0 * H_ + col) =
            packh2(ctxa[nf][0] * inv0, ctxa[nf][1] * inv0);
        *reinterpret_cast<uint32_t*>(Cp + (size_t)(row0 + 8) * H_ + col) =
            packh2(ctxa[nf][2] * inv1, ctxa[nf][3] * inv1);
    }
}

// ---------------------------------------------------------------------------
extern "C" void kernel_launch(void* const* d_in, const int* in_sizes, int n_in,
                              void* d_out, int out_size)
{
    const float* query = (const float*)d_in[0];
    const float* key_  = (const float*)d_in[1];
    const float* value = (const float*)d_in[2];
    const float* Wq = (const float*)d_in[3];
    const float* bq = (const float*)d_in[4];
    const float* Wk = (const float*)d_in[5];
    const float* bk = (const float*)d_in[6];
    const float* Wv = (const float*)d_in[7];
    const float* bv = (const float*)d_in[8];
    const float* Wo = (const float*)d_in[9];
    const float* bo = (const float*)d_in[10];
    float* out = (float*)d_out;

    __half *hin, *hw, *hq, *hk, *hvt, *hctx;
    cudaGetSymbolAddress((void**)&hin,  g_hin);
    cudaGetSymbolAddress((void**)&hw,   g_hw);
    cudaGetSymbolAddress((void**)&hq,   g_hq);
    cudaGetSymbolAddress((void**)&hk,   g_hk);
    cudaGetSymbolAddress((void**)&hvt,  g_hvt);
    cudaGetSymbolAddress((void**)&hctx, g_hctx);

    const size_t NIN = (size_t)B_ * S_ * H_;
    const size_t NW  = (size_t)H_ * H_;

    // fp32 -> fp16 conversions: 2 merged launches.
    f2h3_kernel<<<dim3((int)(NIN / 4 / 256), 3), 256>>>(
        (const float4*)query, (const float4*)key_, (const float4*)value,
        (uint2*)hin, (int)(NIN / 4));
    f2h4_kernel<<<dim3((int)(NW / 4 / 256), 4), 256>>>(
        (const float4*)Wq, (const float4*)Wk, (const float4*)Wv,
        (const float4*)Wo, (uint2*)hw, (int)(NW / 4));

    cudaFuncSetAttribute(proj_kernel,
                         cudaFuncAttributeMaxDynamicSharedMemorySize, SMEM_BYTES);
    cudaFuncSetAttribute(out_kernel,
                         cudaFuncAttributeMaxDynamicSharedMemorySize, SMEM_BYTES);
    cudaFuncSetAttribute(flash_attn,
                         cudaFuncAttributeMaxDynamicSharedMemorySize, FLASH_SMEM);

    const dim3 gproj(H_ / TN, (B_ * S_) / TM, 3);   // (16, 32, 3)
    const dim3 gout(H_ / TN, (B_ * S_) / TM, 1);    // (16, 32)
    const dim3 gfa(S_ / 128, NH_, B_);              // (16, 16, 2)

    // Q/K/V projections in one launch (bias fused; V stored transposed).
    proj_kernel<<<gproj, 256, SMEM_BYTES>>>(hin, hw, hq, hk, hvt, bq, bk, bv);

    flash_attn<<<gfa, 256, FLASH_SMEM>>>(hq, hk, hvt, hctx);

    out_kernel<<<gout, 256, SMEM_BYTES>>>(hctx, hw + 3 * NW, out, bo);
}

// round 16
// speedup vs baseline: 1.0862x; 1.0268x over previous
#include <cuda_runtime.h>
#include <cuda_fp16.h>
#include <cstdint>

// Problem constants
constexpr int B_  = 2;
constexpr int S_  = 2048;
constexpr int H_  = 2048;
constexpr int NH_ = 16;
constexpr int HD_ = 128;
constexpr float SC_L2E = 0.12751743159532244f;   // (1/sqrt(128)) * log2(e)

// Scratch (static device arrays; allocation APIs are forbidden)
__device__ __half g_hin[3 * (size_t)B_ * S_ * H_];   // fp16 query/key/value
__device__ __half g_hw [4 * (size_t)H_ * H_];        // fp16 Wq/Wk/Wv/Wo
__device__ __half g_hq [(size_t)B_ * S_ * H_];       // q proj (fp16)
__device__ __half g_hk [(size_t)B_ * S_ * H_];       // k proj (fp16)
__device__ __half g_hv [(size_t)B_ * S_ * H_];       // v proj (fp16, row-major)
__device__ __half g_hctx[(size_t)B_ * S_ * H_];      // attention output (fp16)

// GEMM tiling: CTA 128x128, k-chunk 64 halves (128B rows), 3-stage cp.async,
// 256 threads = 8 warps (2m x 4n), warp tile 64x32, 2 CTAs/SM.
constexpr int TM = 128, TN = 128, KC = 64, STAGES = 3;
constexpr int A_BYTES   = TM * 128;                      // 16384
constexpr int B_BYTES   = TN * 128;                      // 16384
constexpr int STG_BYTES = A_BYTES + B_BYTES;             // 32768
constexpr int SMEM_BYTES = STAGES * STG_BYTES;           // 98304 (x2 CTA = 192K)

// Flash kernel smem: Q (2 sub-tiles of 128x64h) + 3-stage K,V ring.
constexpr int FT = 16384;                    // one 128x64-half sub-tile
constexpr int OFF_Q  = 0;                    // 2 sub-tiles = 32 KB
constexpr int OFF_KV = 2 * FT;               // 3 stages x (K 2FT + V 2FT)
constexpr int KV_STG = 4 * FT;               // 64 KB per stage
constexpr int FLASH_SMEM = 2 * FT + 3 * KV_STG;          // 229376 B

// ---------------------------------------------------------------------------
__device__ __forceinline__ uint32_t smem_u32(const void* p) {
    uint32_t a;
    asm("{ .reg .u64 t; cvta.to.shared.u64 t, %1; cvt.u32.u64 %0, t; }"
        : "=r"(a) : "l"(p));
    return a;
}
__device__ __forceinline__ void cpa16(uint32_t d, const void* s) {
    asm volatile("cp.async.cg.shared.global [%0], [%1], 16;" :: "r"(d), "l"(s));
}
__device__ __forceinline__ void mma16(float* c, const uint32_t* a,
                                      const uint32_t* b) {
    asm volatile(
        "mma.sync.aligned.m16n8k16.row.col.f32.f16.f16.f32 "
        "{%0,%1,%2,%3},{%4,%5,%6,%7},{%8,%9},{%0,%1,%2,%3};"
        : "+f"(c[0]), "+f"(c[1]), "+f"(c[2]), "+f"(c[3])
        : "r"(a[0]), "r"(a[1]), "r"(a[2]), "r"(a[3]), "r"(b[0]), "r"(b[1]));
}
__device__ __forceinline__ uint32_t packh2(float x, float y) {
    const __half2 h = __floats2half2_rn(x, y);
    return *reinterpret_cast<const uint32_t*>(&h);
}

// fp32 -> fp16: 3 equal-size inputs (query/key/value), one launch.
__global__ __launch_bounds__(256) void f2h3_kernel(
    const float4* __restrict__ x0, const float4* __restrict__ x1,
    const float4* __restrict__ x2, uint2* __restrict__ y, int n4)
{
    const int i = blockIdx.x * 256 + threadIdx.x;
    const float4* src = (blockIdx.y == 0) ? x0 : (blockIdx.y == 1) ? x1 : x2;
    const float4 v = src[i];
    y[(size_t)blockIdx.y * n4 + i] = make_uint2(packh2(v.x, v.y),
                                                packh2(v.z, v.w));
}
// fp32 -> fp16: 4 equal-size weights, one launch.
__global__ __launch_bounds__(256) void f2h4_kernel(
    const float4* __restrict__ x0, const float4* __restrict__ x1,
    const float4* __restrict__ x2, const float4* __restrict__ x3,
    uint2* __restrict__ y, int n4)
{
    const int i = blockIdx.x * 256 + threadIdx.x;
    const float4* src = (blockIdx.y == 0) ? x0 : (blockIdx.y == 1) ? x1
                      : (blockIdx.y == 2) ? x2 : x3;
    const float4 v = src[i];
    y[(size_t)blockIdx.y * n4 + i] = make_uint2(packh2(v.x, v.y),
                                                packh2(v.z, v.w));
}

// ---------------------------------------------------------------------------
// Shared GEMM mainloop (256 threads, 128x128 tile): acc = A-tile @ B-tile^T.
// ---------------------------------------------------------------------------
__device__ __forceinline__ void gemm_mainloop(
    const __half* __restrict__ A, int lda,
    const __half* __restrict__ Bm, int ldb,
    char* smc, float acc[4][4][4], int K)
{
    const uint32_t sbase = smem_u32(smc);
    const int tid = threadIdx.x;
    const int lane = tid & 31, wid = tid >> 5;
    const int g = lane >> 2, tg = lane & 3;
    const int wm = (wid >> 2) * 64, wn = (wid & 3) * 32;
    const int r8 = tid >> 3, c8 = tid & 7;
    const int sc8 = ((c8 ^ (r8 & 7)) << 4);
    const int KIT = K / KC;

    auto stage_load = [&](int s, int kt) {
        const __half* Ak = A + kt * KC;
        const __half* Bk = Bm + kt * KC;
        const uint32_t ab = sbase + (uint32_t)(s * STG_BYTES);
        const uint32_t bb = ab + A_BYTES;
#pragma unroll
        for (int j = 0; j < 4; j++) {
            const int r = r8 + 32 * j;
            cpa16(ab + r * 128 + sc8, Ak + (size_t)r * lda + c8 * 8);
        }
#pragma unroll
        for (int j = 0; j < 4; j++) {
            const int r = r8 + 32 * j;
            cpa16(bb + r * 128 + sc8, Bk + (size_t)r * ldb + c8 * 8);
        }
        asm volatile("cp.async.commit_group;" ::: "memory");
    };

    stage_load(0, 0);
    stage_load(1, 1);

    for (int kt = 0; kt < KIT; kt++) {
        if (kt + 1 < KIT) {
            asm volatile("cp.async.wait_group 1;" ::: "memory");
        } else {
            asm volatile("cp.async.wait_group 0;" ::: "memory");
        }
        __syncthreads();
        if (kt + 2 < KIT) stage_load((kt + 2) % STAGES, kt + 2);

        const char* Ab = smc + (kt % STAGES) * STG_BYTES;
        const char* Bb = Ab + A_BYTES;

#pragma unroll
        for (int h = 0; h < 2; h++) {
            const int cb = ((2 * tg + h) ^ g) << 4;
            uint4 va[4][2], vb[4];
#pragma unroll
            for (int mf = 0; mf < 4; mf++) {
                const int rg = wm + mf * 16 + g;
                va[mf][0] = *(const uint4*)(Ab + rg * 128 + cb);
                va[mf][1] = *(const uint4*)(Ab + (rg + 8) * 128 + cb);
            }
#pragma unroll
            for (int nf = 0; nf < 4; nf++)
                vb[nf] = *(const uint4*)(Bb + (wn + nf * 8 + g) * 128 + cb);

#pragma unroll
            for (int s = 0; s < 2; s++) {
                uint32_t af[4][4], bf[4][2];
#pragma unroll
                for (int mf = 0; mf < 4; mf++) {
                    const uint32_t* u0 = (const uint32_t*)&va[mf][0];
                    const uint32_t* u1 = (const uint32_t*)&va[mf][1];
                    af[mf][0] = u0[2 * s];
                    af[mf][1] = u1[2 * s];
                    af[mf][2] = u0[2 * s + 1];
                    af[mf][3] = u1[2 * s + 1];
                }
#pragma unroll
                for (int nf = 0; nf < 4; nf++) {
                    const uint32_t* u = (const uint32_t*)&vb[nf];
                    bf[nf][0] = u[2 * s];
                    bf[nf][1] = u[2 * s + 1];
                }
#pragma unroll
                for (int mf = 0; mf < 4; mf++)
#pragma unroll
                    for (int nf = 0; nf < 4; nf++)
                        mma16(acc[mf][nf], af[mf], bf[nf]);
            }
        }
    }
}

// ---------------------------------------------------------------------------
// Merged Q/K/V projection — now fully uniform: all outputs row-major fp16.
// ---------------------------------------------------------------------------
__global__ __launch_bounds__(256, 2) void proj_kernel(
    const __half* __restrict__ hin, const __half* __restrict__ hw,
    __half* __restrict__ hq, __half* __restrict__ hk,
    __half* __restrict__ hv,
    const float* __restrict__ bq, const float* __restrict__ bk,
    const float* __restrict__ bv)
{
    extern __shared__ char smc[];
    const int z = blockIdx.z;
    const size_t NIN = (size_t)B_ * S_ * H_;
    const size_t NW  = (size_t)H_ * H_;
    const int m0 = blockIdx.y * TM, n0 = blockIdx.x * TN;

    const __half* A  = hin + z * NIN + (size_t)m0 * H_;
    const __half* Bm = hw + z * NW + (size_t)n0 * H_;
    const float* bias = (z == 0) ? bq : (z == 1) ? bk : bv;
    __half* C = (z == 0) ? hq : (z == 1) ? hk : hv;

    float acc[4][4][4];
#pragma unroll
    for (int i = 0; i < 4; i++)
#pragma unroll
        for (int j = 0; j < 4; j++)
#pragma unroll
            for (int l = 0; l < 4; l++) acc[i][j][l] = 0.0f;

    gemm_mainloop(A, H_, Bm, H_, smc, acc, H_);

    const int lane = threadIdx.x & 31, wid = threadIdx.x >> 5;
    const int g = lane >> 2, tg = lane & 3;
    const int wm = (wid >> 2) * 64, wn = (wid & 3) * 32;

#pragma unroll
    for (int mf = 0; mf < 4; mf++) {
#pragma unroll
        for (int hf = 0; hf < 2; hf++) {
            const int mg = m0 + wm + mf * 16 + g + hf * 8;
#pragma unroll
            for (int nf = 0; nf < 4; nf++) {
                const int cl = wn + nf * 8 + 2 * tg;
                const float v0 = acc[mf][nf][hf * 2 + 0] + bias[n0 + cl];
                const float v1 = acc[mf][nf][hf * 2 + 1] + bias[n0 + cl + 1];
                *reinterpret_cast<uint32_t*>(
                    C + (size_t)mg * H_ + n0 + cl) = packh2(v0, v1);
            }
        }
    }
}

// Final output GEMM: out = hctx @ Wo^T + bo (fp32 store).
__global__ __launch_bounds__(256, 2) void out_kernel(
    const __half* __restrict__ hctx, const __half* __restrict__ hwo,
    float* __restrict__ out, const float* __restrict__ bo)
{
    extern __shared__ char smc[];
    const int m0 = blockIdx.y * TM, n0 = blockIdx.x * TN;
    const __half* A  = hctx + (size_t)m0 * H_;
    const __half* Bm = hwo + (size_t)n0 * H_;

    float acc[4][4][4];
#pragma unroll
    for (int i = 0; i < 4; i++)
#pragma unroll
        for (int j = 0; j < 4; j++)
#pragma unroll
            for (int l = 0; l < 4; l++) acc[i][j][l] = 0.0f;

    gemm_mainloop(A, H_, Bm, H_, smc, acc, H_);

    const int lane = threadIdx.x & 31, wid = threadIdx.x >> 5;
    const int g = lane >> 2, tg = lane & 3;
    const int wm = (wid >> 2) * 64, wn = (wid & 3) * 32;

#pragma unroll
    for (int mf = 0; mf < 4; mf++) {
#pragma unroll
        for (int hf = 0; hf < 2; hf++) {
            const int mg = m0 + wm + mf * 16 + g + hf * 8;
#pragma unroll
            for (int nf = 0; nf < 4; nf++) {
                const int cl = wn + nf * 8 + 2 * tg;
                const float v0 = acc[mf][nf][hf * 2 + 0] + bo[n0 + cl];
                const float v1 = acc[mf][nf][hf * 2 + 1] + bo[n0 + cl + 1];
                *reinterpret_cast<float2*>(
                    out + (size_t)mg * H_ + n0 + cl) = make_float2(v0, v1);
            }
        }
    }
}

// ---------------------------------------------------------------------------
// Fused flash attention: per CTA = (b, h, 128-row q-tile).
// V is row-major [s][d]; ctx B-fragments come via ldmatrix.x4.trans:
//   matrices = (k-lo/k-hi) x (n-lo/n-hi) quadrants of a 16x16 V block.
// ---------------------------------------------------------------------------
__global__ __launch_bounds__(256, 1) void flash_attn(
    const __half* __restrict__ hq, const __half* __restrict__ hk,
    const __half* __restrict__ hv, __half* __restrict__ hctx)
{
    extern __shared__ char smc[];
    const uint32_t sb = smem_u32(smc);
    const int tid = threadIdx.x, lane = tid & 31, w = tid >> 5;
    const int g = lane >> 2, tg = lane & 3;
    const int zh = blockIdx.y, zb = blockIdx.z;
    const int q0 = blockIdx.x * 128;
    const size_t sSH = (size_t)S_ * H_;

    const __half* Qg = hq + zb * sSH + (size_t)q0 * H_ + zh * HD_;
    const __half* Kg = hk + zb * sSH + zh * HD_;
    const __half* Vg = hv + zb * sSH + zh * HD_;   // row-major, same as K

    const int r8 = tid >> 3, c8 = tid & 7;

    auto stage = [&](uint32_t dst, const __half* gp, int stride) {
#pragma unroll
        for (int j = 0; j < 4; j++) {
            const int r = r8 + 32 * j;
            cpa16(sb + dst + r * 128 + ((c8 ^ (r & 7)) << 4),
                  gp + (size_t)r * stride + c8 * 8);
        }
    };
    auto load_kv = [&](int j) {
        const __half* kp = Kg + (size_t)(j * 128) * H_;
        const __half* vp = Vg + (size_t)(j * 128) * H_;
        const uint32_t kd = OFF_KV + (j % 3) * KV_STG;
        const uint32_t vd = kd + 2 * FT;
        stage(kd, kp, H_);      stage(kd + FT, kp + 64, H_);
        stage(vd, vp, H_);      stage(vd + FT, vp + 64, H_);
        asm volatile("cp.async.commit_group;" ::: "memory");
    };

    // Prologue: group0 = Q + KV0, group1 = KV1.
    stage(OFF_Q, Qg, H_);
    stage(OFF_Q + FT, Qg + 64, H_);
    {
        stage(OFF_KV, Kg, H_);
        stage(OFF_KV + FT, Kg + 64, H_);
        stage(OFF_KV + 2 * FT, Vg, H_);
        stage(OFF_KV + 3 * FT, Vg + 64, H_);
        asm volatile("cp.async.commit_group;" ::: "memory");
    }
    load_kv(1);

    float ctxa[16][4];
#pragma unroll
    for (int i = 0; i < 16; i++)
#pragma unroll
        for (int l = 0; l < 4; l++) ctxa[i][l] = 0.0f;
    float rs0 = 0.f, rs1 = 0.f;
    uint4 qv[2][2][2];           // [sub-tile][h-slice][row g / g+8]

    // ldmatrix.trans per-lane geometry: mi = quadrant index.
    const int lrt = lane & 7, mi = lane >> 3;
    const int kodd = mi & 1, nodd = (mi >> 1) & 1;
    const int vrow_off = (8 * kodd + lrt) * 128;   // + 16c*128 per k-block

    for (int j = 0; j < 16; j++) {
        if (j < 15) {
            asm volatile("cp.async.wait_group 1;" ::: "memory");
        } else {
            asm volatile("cp.async.wait_group 0;" ::: "memory");
        }
        __syncthreads();
        if (j + 2 < 16) load_kv(j + 2);

        const char* Kb = smc + OFF_KV + (j % 3) * KV_STG;
        const uint32_t Vb = sb + OFF_KV + (j % 3) * KV_STG + 2 * FT;

        if (j == 0) {
            const char* Qb = smc + OFF_Q;
#pragma unroll
            for (int st = 0; st < 2; st++)
#pragma unroll
                for (int h = 0; h < 2; h++) {
                    const int cb = ((2 * tg + h) ^ g) << 4;
                    const int rg = w * 16 + g;
                    qv[st][h][0] = *(const uint4*)(Qb + st * FT + rg * 128 + cb);
                    qv[st][h][1] = *(const uint4*)(Qb + st * FT + (rg + 8) * 128 + cb);
                }
        }

        // ---- scores: S = Q @ K_j^T (k-permuted frags, exact) ----
        float sacc[16][4];
#pragma unroll
        for (int i = 0; i < 16; i++)
#pragma unroll
            for (int l = 0; l < 4; l++) sacc[i][l] = 0.0f;

#pragma unroll
        for (int st = 0; st < 2; st++)
#pragma unroll
            for (int h = 0; h < 2; h++) {
                const int cb = ((2 * tg + h) ^ g) << 4;
                const char* Kst = Kb + st * FT;
                uint32_t af[2][4];
                {
                    const uint32_t* u0 = (const uint32_t*)&qv[st][h][0];
                    const uint32_t* u1 = (const uint32_t*)&qv[st][h][1];
#pragma unroll
                    for (int s = 0; s < 2; s++) {
                        af[s][0] = u0[2 * s];
                        af[s][1] = u1[2 * s];
                        af[s][2] = u0[2 * s + 1];
                        af[s][3] = u1[2 * s + 1];
                    }
                }
#pragma unroll
                for (int half = 0; half < 2; half++) {
                    uint4 vb[8];
#pragma unroll
                    for (int nb = 0; nb < 8; nb++)
                        vb[nb] = *(const uint4*)(
                            Kst + (64 * half + 8 * nb + g) * 128 + cb);
#pragma unroll
                    for (int s = 0; s < 2; s++)
#pragma unroll
                        for (int nb = 0; nb < 8; nb++) {
                            const uint32_t* u = (const uint32_t*)&vb[nb];
                            uint32_t bf[2] = {u[2 * s], u[2 * s + 1]};
                            mma16(sacc[8 * half + nb], af[s], bf);
                        }
                }
            }

        // ---- exp + rowsum + repack to fp16 A-fragments (registers only) ----
        uint32_t P[8][4];
#pragma unroll
        for (int c = 0; c < 8; c++) {
            float e0 = exp2f(sacc[2 * c][0] * SC_L2E);
            float e1 = exp2f(sacc[2 * c][1] * SC_L2E);
            float e2 = exp2f(sacc[2 * c][2] * SC_L2E);
            float e3 = exp2f(sacc[2 * c][3] * SC_L2E);
            float f0 = exp2f(sacc[2 * c + 1][0] * SC_L2E);
            float f1 = exp2f(sacc[2 * c + 1][1] * SC_L2E);
            float f2 = exp2f(sacc[2 * c + 1][2] * SC_L2E);
            float f3 = exp2f(sacc[2 * c + 1][3] * SC_L2E);
            rs0 += (e0 + e1) + (f0 + f1);
            rs1 += (e2 + e3) + (f2 + f3);
            P[c][0] = packh2(e0, e1);
            P[c][1] = packh2(e2, e3);
            P[c][2] = packh2(f0, f1);
            P[c][3] = packh2(f2, f3);
        }

        // ---- ctx += P @ V_j (row-major V, ldmatrix.x4.trans) ----
#pragma unroll
        for (int c = 0; c < 8; c++) {
            const uint32_t rowb = vrow_off + c * 16 * 128;
#pragma unroll
            for (int np = 0; np < 8; np++) {
                const uint32_t Vst = Vb + (np >> 2) * FT;
                const int chunk = (((np & 3) * 2 + nodd) ^ lrt) << 4;
                const uint32_t addr = Vst + rowb + chunk;
                uint32_t b0, b1, b2, b3;
                asm volatile(
                    "ldmatrix.sync.aligned.m8n8.x4.trans.shared.b16 "
                    "{%0,%1,%2,%3}, [%4];"
                    : "=r"(b0), "=r"(b1), "=r"(b2), "=r"(b3) : "r"(addr));
                uint32_t bfa[2] = {b0, b1}, bfb[2] = {b2, b3};
                mma16(ctxa[2 * np], P[c], bfa);
                mma16(ctxa[2 * np + 1], P[c], bfb);
            }
        }
    }

    // ---- epilogue: normalize by row sums, store fp16 ctx ----
#pragma unroll
    for (int off = 1; off < 4; off <<= 1) {
        rs0 += __shfl_xor_sync(0xffffffffu, rs0, off);
        rs1 += __shfl_xor_sync(0xffffffffu, rs1, off);
    }
    const float inv0 = 1.0f / rs0, inv1 = 1.0f / rs1;

    const int row0 = q0 + w * 16 + g;
    __half* Cp = hctx + zb * sSH + zh * HD_;
#pragma unroll
    for (int nf = 0; nf < 16; nf++) {
        const int col = nf * 8 + 2 * tg;
        *reinterpret_cast<uint32_t*>(Cp + (size_t)row0 * H_ + col) =
            packh2(ctxa[nf][0] * inv0, ctxa[nf][1] * inv0);
        *reinterpret_cast<uint32_t*>(Cp + (size_t)(row0 + 8) * H_ + col) =
            packh2(ctxa[nf][2] * inv1, ctxa[nf][3] * inv1);
    }
}

// ---------------------------------------------------------------------------
extern "C" void kernel_launch(void* const* d_in, const int* in_sizes, int n_in,
                              void* d_out, int out_size)
{
    const float* query = (const float*)d_in[0];
    const float* key_  = (const float*)d_in[1];
    const float* value = (const float*)d_in[2];
    const float* Wq = (const float*)d_in[3];
    const float* bq = (const float*)d_in[4];
    const float* Wk = (const float*)d_in[5];
    const float* bk = (const float*)d_in[6];
    const float* Wv = (const float*)d_in[7];
    const float* bv = (const float*)d_in[8];
    const float* Wo = (const float*)d_in[9];
    const float* bo = (const float*)d_in[10];
    float* out = (float*)d_out;

    __half *hin, *hw, *hq, *hk, *hv, *hctx;
    cudaGetSymbolAddress((void**)&hin,  g_hin);
    cudaGetSymbolAddress((void**)&hw,   g_hw);
    cudaGetSymbolAddress((void**)&hq,   g_hq);
    cudaGetSymbolAddress((void**)&hk,   g_hk);
    cudaGetSymbolAddress((void**)&hv,   g_hv);
    cudaGetSymbolAddress((void**)&hctx, g_hctx);

    const size_t NIN = (size_t)B_ * S_ * H_;
    const size_t NW  = (size_t)H_ * H_;

    // fp32 -> fp16 conversions: 2 merged launches.
    f2h3_kernel<<<dim3((int)(NIN / 4 / 256), 3), 256>>>(
        (const float4*)query, (const float4*)key_, (const float4*)value,
        (uint2*)hin, (int)(NIN / 4));
    f2h4_kernel<<<dim3((int)(NW / 4 / 256), 4), 256>>>(
        (const float4*)Wq, (const float4*)Wk, (const float4*)Wv,
        (const float4*)Wo, (uint2*)hw, (int)(NW / 4));

    cudaFuncSetAttribute(proj_kernel,
                         cudaFuncAttributeMaxDynamicSharedMemorySize, SMEM_BYTES);
    cudaFuncSetAttribute(out_kernel,
                         cudaFuncAttributeMaxDynamicSharedMemorySize, SMEM_BYTES);
    cudaFuncSetAttribute(flash_attn,
                         cudaFuncAttributeMaxDynamicSharedMemorySize, FLASH_SMEM);

    const dim3 gproj(H_ / TN, (B_ * S_) / TM, 3);   // (16, 32, 3)
    const dim3 gout(H_ / TN, (B_ * S_) / TM, 1);    // (16, 32)
    const dim3 gfa(S_ / 128, NH_, B_);              // (16, 16, 2)

    // Q/K/V projections in one launch (bias fused; all row-major now).
    proj_kernel<<<gproj, 256, SMEM_BYTES>>>(hin, hw, hq, hk, hv, bq, bk, bv);

    flash_attn<<<gfa, 256, FLASH_SMEM>>>(hq, hk, hv, hctx);

    out_kernel<<<gout, 256, SMEM_BYTES>>>(hctx, hw + 3 * NW, out, bo);
}

// round 17
// speedup vs baseline: 1.0941x; 1.0073x over previous
#include <cuda_runtime.h>
#include <cuda_fp16.h>
#include <cstdint>

// Problem constants
constexpr int B_  = 2;
constexpr int S_  = 2048;
constexpr int H_  = 2048;
constexpr int NH_ = 16;
constexpr int HD_ = 128;
constexpr float SC_L2E = 0.12751743159532244f;   // (1/sqrt(128)) * log2(e)

// Scratch (static device arrays; allocation APIs are forbidden)
__device__ __half g_hin[3 * (size_t)B_ * S_ * H_];   // fp16 query/key/value
__device__ __half g_hw [4 * (size_t)H_ * H_];        // fp16 Wq/Wk/Wv/Wo
__device__ __half g_hq [(size_t)B_ * S_ * H_];       // q proj (fp16)
__device__ __half g_hk [(size_t)B_ * S_ * H_];       // k proj (fp16)
__device__ __half g_hv [(size_t)B_ * S_ * H_];       // v proj (fp16, row-major)
__device__ __half g_hctx[(size_t)B_ * S_ * H_];      // attention output (fp16)
__device__ int    g_cnt[32];                         // flash->out readiness

// GEMM tiling: CTA 128x128, k-chunk 64 halves (128B rows), 3-stage cp.async.
constexpr int TM = 128, TN = 128, KC = 64, STAGES = 3;
constexpr int A_BYTES   = TM * 128;                      // 16384
constexpr int B_BYTES   = TN * 128;                      // 16384
constexpr int STG_BYTES = A_BYTES + B_BYTES;             // 32768
constexpr int SMEM_BYTES = STAGES * STG_BYTES;           // 98304

// Flash smem: Q (2 sub-tiles of 128x64h) + 3-stage K,V ring.
constexpr int FT = 16384;                    // one 128x64-half sub-tile
constexpr int OFF_Q  = 0;                    // 2 sub-tiles = 32 KB
constexpr int OFF_KV = 2 * FT;               // 3 stages x (K 2FT + V 2FT)
constexpr int KV_STG = 4 * FT;               // 64 KB per stage
constexpr int FLASH_SMEM = 2 * FT + 3 * KV_STG;          // 229376 B

// ---------------------------------------------------------------------------
__device__ __forceinline__ uint32_t smem_u32(const void* p) {
    uint32_t a;
    asm("{ .reg .u64 t; cvta.to.shared.u64 t, %1; cvt.u32.u64 %0, t; }"
        : "=r"(a) : "l"(p));
    return a;
}
__device__ __forceinline__ void cpa16(uint32_t d, const void* s) {
    asm volatile("cp.async.cg.shared.global [%0], [%1], 16;" :: "r"(d), "l"(s));
}
__device__ __forceinline__ void mma16(float* c, const uint32_t* a,
                                      const uint32_t* b) {
    asm volatile(
        "mma.sync.aligned.m16n8k16.row.col.f32.f16.f16.f32 "
        "{%0,%1,%2,%3},{%4,%5,%6,%7},{%8,%9},{%0,%1,%2,%3};"
        : "+f"(c[0]), "+f"(c[1]), "+f"(c[2]), "+f"(c[3])
        : "r"(a[0]), "r"(a[1]), "r"(a[2]), "r"(a[3]), "r"(b[0]), "r"(b[1]));
}
__device__ __forceinline__ uint32_t packh2(float x, float y) {
    const __half2 h = __floats2half2_rn(x, y);
    return *reinterpret_cast<const uint32_t*>(&h);
}

// Single fp32->fp16 conversion kernel: y 0-2 inputs, y 3-6 weights.
// Also resets the flash->out readiness counters (block x==0,y==0).
__global__ __launch_bounds__(256) void f2h_all(
    const float4* __restrict__ q32, const float4* __restrict__ k32,
    const float4* __restrict__ v32,
    const float4* __restrict__ wq, const float4* __restrict__ wk,
    const float4* __restrict__ wv, const float4* __restrict__ wo,
    uint2* __restrict__ hin, uint2* __restrict__ hw, int n4in, int n4w)
{
    if (blockIdx.x == 0 && blockIdx.y == 0 && threadIdx.x < 32)
        g_cnt[threadIdx.x] = 0;
    const int y = blockIdx.y;
    const int i = blockIdx.x * 256 + threadIdx.x;
    if (y < 3) {
        const float4* src = (y == 0) ? q32 : (y == 1) ? k32 : v32;
        const float4 v = src[i];
        hin[(size_t)y * n4in + i] = make_uint2(packh2(v.x, v.y),
                                               packh2(v.z, v.w));
    } else if (i < n4w) {
        const int wsel = y - 3;
        const float4* src = (wsel == 0) ? wq : (wsel == 1) ? wk
                          : (wsel == 2) ? wv : wo;
        const float4 v = src[i];
        hw[(size_t)wsel * n4w + i] = make_uint2(packh2(v.x, v.y),
                                                packh2(v.z, v.w));
    }
}

// ---------------------------------------------------------------------------
// Shared GEMM mainloop (256 threads, 128x128 tile): acc = A-tile @ B-tile^T.
// ---------------------------------------------------------------------------
__device__ __forceinline__ void gemm_mainloop(
    const __half* __restrict__ A, int lda,
    const __half* __restrict__ Bm, int ldb,
    char* smc, float acc[4][4][4], int K)
{
    const uint32_t sbase = smem_u32(smc);
    const int tid = threadIdx.x;
    const int lane = tid & 31, wid = tid >> 5;
    const int g = lane >> 2, tg = lane & 3;
    const int wm = (wid >> 2) * 64, wn = (wid & 3) * 32;
    const int r8 = tid >> 3, c8 = tid & 7;
    const int sc8 = ((c8 ^ (r8 & 7)) << 4);
    const int KIT = K / KC;

    auto stage_load = [&](int s, int kt) {
        const __half* Ak = A + kt * KC;
        const __half* Bk = Bm + kt * KC;
        const uint32_t ab = sbase + (uint32_t)(s * STG_BYTES);
        const uint32_t bb = ab + A_BYTES;
#pragma unroll
        for (int j = 0; j < 4; j++) {
            const int r = r8 + 32 * j;
            cpa16(ab + r * 128 + sc8, Ak + (size_t)r * lda + c8 * 8);
        }
#pragma unroll
        for (int j = 0; j < 4; j++) {
            const int r = r8 + 32 * j;
            cpa16(bb + r * 128 + sc8, Bk + (size_t)r * ldb + c8 * 8);
        }
        asm volatile("cp.async.commit_group;" ::: "memory");
    };

    stage_load(0, 0);
    stage_load(1, 1);

    for (int kt = 0; kt < KIT; kt++) {
        if (kt + 1 < KIT) {
            asm volatile("cp.async.wait_group 1;" ::: "memory");
        } else {
            asm volatile("cp.async.wait_group 0;" ::: "memory");
        }
        __syncthreads();
        if (kt + 2 < KIT) stage_load((kt + 2) % STAGES, kt + 2);

        const char* Ab = smc + (kt % STAGES) * STG_BYTES;
        const char* Bb = Ab + A_BYTES;

#pragma unroll
        for (int h = 0; h < 2; h++) {
            const int cb = ((2 * tg + h) ^ g) << 4;
            uint4 va[4][2], vb[4];
#pragma unroll
            for (int mf = 0; mf < 4; mf++) {
                const int rg = wm + mf * 16 + g;
                va[mf][0] = *(const uint4*)(Ab + rg * 128 + cb);
                va[mf][1] = *(const uint4*)(Ab + (rg + 8) * 128 + cb);
            }
#pragma unroll
            for (int nf = 0; nf < 4; nf++)
                vb[nf] = *(const uint4*)(Bb + (wn + nf * 8 + g) * 128 + cb);

#pragma unroll
            for (int s = 0; s < 2; s++) {
                uint32_t af[4][4], bf[4][2];
#pragma unroll
                for (int mf = 0; mf < 4; mf++) {
                    const uint32_t* u0 = (const uint32_t*)&va[mf][0];
                    const uint32_t* u1 = (const uint32_t*)&va[mf][1];
                    af[mf][0] = u0[2 * s];
                    af[mf][1] = u1[2 * s];
                    af[mf][2] = u0[2 * s + 1];
                    af[mf][3] = u1[2 * s + 1];
                }
#pragma unroll
                for (int nf = 0; nf < 4; nf++) {
                    const uint32_t* u = (const uint32_t*)&vb[nf];
                    bf[nf][0] = u[2 * s];
                    bf[nf][1] = u[2 * s + 1];
                }
#pragma unroll
                for (int mf = 0; mf < 4; mf++)
#pragma unroll
                    for (int nf = 0; nf < 4; nf++)
                        mma16(acc[mf][nf], af[mf], bf[nf]);
            }
        }
    }
}

// ---------------------------------------------------------------------------
// Merged Q/K/V projection: all outputs row-major fp16. 2 CTAs/SM.
// ---------------------------------------------------------------------------
__global__ __launch_bounds__(256, 2) void proj_kernel(
    const __half* __restrict__ hin, const __half* __restrict__ hw,
    __half* __restrict__ hq, __half* __restrict__ hk,
    __half* __restrict__ hv,
    const float* __restrict__ bq, const float* __restrict__ bk,
    const float* __restrict__ bv)
{
    extern __shared__ char smc[];
    const int z = blockIdx.z;
    const size_t NIN = (size_t)B_ * S_ * H_;
    const size_t NW  = (size_t)H_ * H_;
    const int m0 = blockIdx.y * TM, n0 = blockIdx.x * TN;

    const __half* A  = hin + z * NIN + (size_t)m0 * H_;
    const __half* Bm = hw + z * NW + (size_t)n0 * H_;
    const float* bias = (z == 0) ? bq : (z == 1) ? bk : bv;
    __half* C = (z == 0) ? hq : (z == 1) ? hk : hv;

    float acc[4][4][4];
#pragma unroll
    for (int i = 0; i < 4; i++)
#pragma unroll
        for (int j = 0; j < 4; j++)
#pragma unroll
            for (int l = 0; l < 4; l++) acc[i][j][l] = 0.0f;

    gemm_mainloop(A, H_, Bm, H_, smc, acc, H_);

    const int lane = threadIdx.x & 31, wid = threadIdx.x >> 5;
    const int g = lane >> 2, tg = lane & 3;
    const int wm = (wid >> 2) * 64, wn = (wid & 3) * 32;

#pragma unroll
    for (int mf = 0; mf < 4; mf++) {
#pragma unroll
        for (int hf = 0; hf < 2; hf++) {
            const int mg = m0 + wm + mf * 16 + g + hf * 8;
#pragma unroll
            for (int nf = 0; nf < 4; nf++) {
                const int cl = wn + nf * 8 + 2 * tg;
                const float v0 = acc[mf][nf][hf * 2 + 0] + bias[n0 + cl];
                const float v1 = acc[mf][nf][hf * 2 + 1] + bias[n0 + cl + 1];
                *reinterpret_cast<uint32_t*>(
                    C + (size_t)mg * H_ + n0 + cl) = packh2(v0, v1);
            }
        }
    }
}

// ---------------------------------------------------------------------------
// Fused flash attention + output GEMM in ONE launch.
//   bids [0,512):   flash work unit (b, h, 128-row q-tile); signals counter.
//   bids [512,1024): out tile; spins until its (b, q-tile) has all 16 heads.
// Deadlock-safe: out bid 512+u depends only on flash bids <= 256b+255 < 512,
// which precede it by >=257 positions in hardware CTA issue order.
// ---------------------------------------------------------------------------
__global__ __launch_bounds__(256, 1) void fused_attn_out(
    const __half* __restrict__ hq, const __half* __restrict__ hk,
    const __half* __restrict__ hv, __half* __restrict__ hctx,
    const __half* __restrict__ hwo, float* __restrict__ out,
    const float* __restrict__ bo)
{
    extern __shared__ char smc[];
    const int bid = blockIdx.x;
    const int tid = threadIdx.x;

    if (bid >= 512) {
        // ================= OUT tile =================
        const int u = bid - 512;
        const int n0 = (u & 15) * TN;
        const int my = u >> 4;               // m-tile 0..31
        const int m0 = my * TM;
        const int cidx = (my >> 4) * 16 + (my & 15);   // b*16 + qt

        if (tid == 0) {
            while (atomicAdd(&g_cnt[cidx], 0) < 16) __nanosleep(64);
            __threadfence();
        }
        __syncthreads();

        const __half* A  = hctx + (size_t)m0 * H_;
        const __half* Bm = hwo + (size_t)n0 * H_;

        float acc[4][4][4];
#pragma unroll
        for (int i = 0; i < 4; i++)
#pragma unroll
            for (int j = 0; j < 4; j++)
#pragma unroll
                for (int l = 0; l < 4; l++) acc[i][j][l] = 0.0f;

        gemm_mainloop(A, H_, Bm, H_, smc, acc, H_);

        const int lane = tid & 31, wid = tid >> 5;
        const int g = lane >> 2, tg = lane & 3;
        const int wm = (wid >> 2) * 64, wn = (wid & 3) * 32;
#pragma unroll
        for (int mf = 0; mf < 4; mf++) {
#pragma unroll
            for (int hf = 0; hf < 2; hf++) {
                const int mg = m0 + wm + mf * 16 + g + hf * 8;
#pragma unroll
                for (int nf = 0; nf < 4; nf++) {
                    const int cl = wn + nf * 8 + 2 * tg;
                    const float v0 = acc[mf][nf][hf * 2 + 0] + bo[n0 + cl];
                    const float v1 = acc[mf][nf][hf * 2 + 1] + bo[n0 + cl + 1];
                    *reinterpret_cast<float2*>(
                        out + (size_t)mg * H_ + n0 + cl) = make_float2(v0, v1);
                }
            }
        }
        return;
    }

    // ================= FLASH work unit =================
    const uint32_t sb = smem_u32(smc);
    const int lane = tid & 31, w = tid >> 5;
    const int g = lane >> 2, tg = lane & 3;
    const int qt = bid & 15, zh = (bid >> 4) & 15, zb = bid >> 8;
    const int q0 = qt * 128;
    const size_t sSH = (size_t)S_ * H_;

    const __half* Qg = hq + zb * sSH + (size_t)q0 * H_ + zh * HD_;
    const __half* Kg = hk + zb * sSH + zh * HD_;
    const __half* Vg = hv + zb * sSH + zh * HD_;

    const int r8 = tid >> 3, c8 = tid & 7;

    auto stage = [&](uint32_t dst, const __half* gp, int stride) {
#pragma unroll
        for (int j = 0; j < 4; j++) {
            const int r = r8 + 32 * j;
            cpa16(sb + dst + r * 128 + ((c8 ^ (r & 7)) << 4),
                  gp + (size_t)r * stride + c8 * 8);
        }
    };
    auto load_kv = [&](int j) {
        const __half* kp = Kg + (size_t)(j * 128) * H_;
        const __half* vp = Vg + (size_t)(j * 128) * H_;
        const uint32_t kd = OFF_KV + (j % 3) * KV_STG;
        const uint32_t vd = kd + 2 * FT;
        stage(kd, kp, H_);      stage(kd + FT, kp + 64, H_);
        stage(vd, vp, H_);      stage(vd + FT, vp + 64, H_);
        asm volatile("cp.async.commit_group;" ::: "memory");
    };

    stage(OFF_Q, Qg, H_);
    stage(OFF_Q + FT, Qg + 64, H_);
    {
        stage(OFF_KV, Kg, H_);
        stage(OFF_KV + FT, Kg + 64, H_);
        stage(OFF_KV + 2 * FT, Vg, H_);
        stage(OFF_KV + 3 * FT, Vg + 64, H_);
        asm volatile("cp.async.commit_group;" ::: "memory");
    }
    load_kv(1);

    float ctxa[16][4];
#pragma unroll
    for (int i = 0; i < 16; i++)
#pragma unroll
        for (int l = 0; l < 4; l++) ctxa[i][l] = 0.0f;
    float rs0 = 0.f, rs1 = 0.f;
    uint4 qv[2][2][2];

    const int lrt = lane & 7, mi = lane >> 3;
    const int kodd = mi & 1, nodd = (mi >> 1) & 1;
    const int vrow_off = (8 * kodd + lrt) * 128;

    for (int j = 0; j < 16; j++) {
        if (j < 15) {
            asm volatile("cp.async.wait_group 1;" ::: "memory");
        } else {
            asm volatile("cp.async.wait_group 0;" ::: "memory");
        }
        __syncthreads();
        if (j + 2 < 16) load_kv(j + 2);

        const char* Kb = smc + OFF_KV + (j % 3) * KV_STG;
        const uint32_t Vb = sb + OFF_KV + (j % 3) * KV_STG + 2 * FT;

        if (j == 0) {
            const char* Qb = smc + OFF_Q;
#pragma unroll
            for (int st = 0; st < 2; st++)
#pragma unroll
                for (int h = 0; h < 2; h++) {
                    const int cb = ((2 * tg + h) ^ g) << 4;
                    const int rg = w * 16 + g;
                    qv[st][h][0] = *(const uint4*)(Qb + st * FT + rg * 128 + cb);
                    qv[st][h][1] = *(const uint4*)(Qb + st * FT + (rg + 8) * 128 + cb);
                }
        }

        float sacc[16][4];
#pragma unroll
        for (int i = 0; i < 16; i++)
#pragma unroll
            for (int l = 0; l < 4; l++) sacc[i][l] = 0.0f;

#pragma unroll
        for (int st = 0; st < 2; st++)
#pragma unroll
            for (int h = 0; h < 2; h++) {
                const int cb = ((2 * tg + h) ^ g) << 4;
                const char* Kst = Kb + st * FT;
                uint32_t af[2][4];
                {
                    const uint32_t* u0 = (const uint32_t*)&qv[st][h][0];
                    const uint32_t* u1 = (const uint32_t*)&qv[st][h][1];
#pragma unroll
                    for (int s = 0; s < 2; s++) {
                        af[s][0] = u0[2 * s];
                        af[s][1] = u1[2 * s];
                        af[s][2] = u0[2 * s + 1];
                        af[s][3] = u1[2 * s + 1];
                    }
                }
#pragma unroll
                for (int half = 0; half < 2; half++) {
                    uint4 vb[8];
#pragma unroll
                    for (int nb = 0; nb < 8; nb++)
                        vb[nb] = *(const uint4*)(
                            Kst + (64 * half + 8 * nb + g) * 128 + cb);
#pragma unroll
                    for (int s = 0; s < 2; s++)
#pragma unroll
                        for (int nb = 0; nb < 8; nb++) {
                            const uint32_t* u = (const uint32_t*)&vb[nb];
                            uint32_t bf[2] = {u[2 * s], u[2 * s + 1]};
                            mma16(sacc[8 * half + nb], af[s], bf);
                        }
                }
            }

        uint32_t P[8][4];
#pragma unroll
        for (int c = 0; c < 8; c++) {
            float e0 = exp2f(sacc[2 * c][0] * SC_L2E);
            float e1 = exp2f(sacc[2 * c][1] * SC_L2E);
            float e2 = exp2f(sacc[2 * c][2] * SC_L2E);
            float e3 = exp2f(sacc[2 * c][3] * SC_L2E);
            float f0 = exp2f(sacc[2 * c + 1][0] * SC_L2E);
            float f1 = exp2f(sacc[2 * c + 1][1] * SC_L2E);
            float f2 = exp2f(sacc[2 * c + 1][2] * SC_L2E);
            float f3 = exp2f(sacc[2 * c + 1][3] * SC_L2E);
            rs0 += (e0 + e1) + (f0 + f1);
            rs1 += (e2 + e3) + (f2 + f3);
            P[c][0] = packh2(e0, e1);
            P[c][1] = packh2(e2, e3);
            P[c][2] = packh2(f0, f1);
            P[c][3] = packh2(f2, f3);
        }

#pragma unroll
        for (int c = 0; c < 8; c++) {
            const uint32_t rowb = vrow_off + c * 16 * 128;
#pragma unroll
            for (int np = 0; np < 8; np++) {
                const uint32_t Vst = Vb + (np >> 2) * FT;
                const int chunk = (((np & 3) * 2 + nodd) ^ lrt) << 4;
                const uint32_t addr = Vst + rowb + chunk;
                uint32_t b0, b1, b2, b3;
                asm volatile(
                    "ldmatrix.sync.aligned.m8n8.x4.trans.shared.b16 "
                    "{%0,%1,%2,%3}, [%4];"
                    : "=r"(b0), "=r"(b1), "=r"(b2), "=r"(b3) : "r"(addr));
                uint32_t bfa[2] = {b0, b1}, bfb[2] = {b2, b3};
                mma16(ctxa[2 * np], P[c], bfa);
                mma16(ctxa[2 * np + 1], P[c], bfb);
            }
        }
    }

#pragma unroll
    for (int off = 1; off < 4; off <<= 1) {
        rs0 += __shfl_xor_sync(0xffffffffu, rs0, off);
        rs1 += __shfl_xor_sync(0xffffffffu, rs1, off);
    }
    const float inv0 = 1.0f / rs0, inv1 = 1.0f / rs1;

    const int row0 = q0 + w * 16 + g;
    __half* Cp = hctx + zb * sSH + zh * HD_;
#pragma unroll
    for (int nf = 0; nf < 16; nf++) {
        const int col = nf * 8 + 2 * tg;
        *reinterpret_cast<uint32_t*>(Cp + (size_t)row0 * H_ + col) =
            packh2(ctxa[nf][0] * inv0, ctxa[nf][1] * inv0);
        *reinterpret_cast<uint32_t*>(Cp + (size_t)(row0 + 8) * H_ + col) =
            packh2(ctxa[nf][2] * inv1, ctxa[nf][3] * inv1);
    }

    // Signal: this (b, q-tile) head is done.
    __threadfence();
    __syncthreads();
    if (tid == 0) atomicAdd(&g_cnt[zb * 16 + qt], 1);
}

// ---------------------------------------------------------------------------
extern "C" void kernel_launch(void* const* d_in, const int* in_sizes, int n_in,
                              void* d_out, int out_size)
{
    const float* query = (const float*)d_in[0];
    const float* key_  = (const float*)d_in[1];
    const float* value = (const float*)d_in[2];
    const float* Wq = (const float*)d_in[3];
    const float* bq = (const float*)d_in[4];
    const float* Wk = (const float*)d_in[5];
    const float* bk = (const float*)d_in[6];
    const float* Wv = (const float*)d_in[7];
    const float* bv = (const float*)d_in[8];
    const float* Wo = (const float*)d_in[9];
    const float* bo = (const float*)d_in[10];
    float* out = (float*)d_out;

    __half *hin, *hw, *hq, *hk, *hv, *hctx;
    cudaGetSymbolAddress((void**)&hin,  g_hin);
    cudaGetSymbolAddress((void**)&hw,   g_hw);
    cudaGetSymbolAddress((void**)&hq,   g_hq);
    cudaGetSymbolAddress((void**)&hk,   g_hk);
    cudaGetSymbolAddress((void**)&hv,   g_hv);
    cudaGetSymbolAddress((void**)&hctx, g_hctx);

    const size_t NIN = (size_t)B_ * S_ * H_;
    const size_t NW  = (size_t)H_ * H_;
    const int n4in = (int)(NIN / 4);   // 2097152
    const int n4w  = (int)(NW / 4);    // 1048576

    // fp32 -> fp16 conversions + counter reset, single launch.
    f2h_all<<<dim3(n4in / 256, 7), 256>>>(
        (const float4*)query, (const float4*)key_, (const float4*)value,
        (const float4*)Wq, (const float4*)Wk, (const float4*)Wv,
        (const float4*)Wo, (uint2*)hin, (uint2*)hw, n4in, n4w);

    cudaFuncSetAttribute(proj_kernel,
                         cudaFuncAttributeMaxDynamicSharedMemorySize, SMEM_BYTES);
    cudaFuncSetAttribute(fused_attn_out,
                         cudaFuncAttributeMaxDynamicSharedMemorySize, FLASH_SMEM);

    const dim3 gproj(H_ / TN, (B_ * S_) / TM, 3);   // (16, 32, 3)

    // Q/K/V projections in one launch (bias fused; all row-major).
    proj_kernel<<<gproj, 256, SMEM_BYTES>>>(hin, hw, hq, hk, hv, bq, bk, bv);

    // Flash attention (bids 0-511) + output GEMM (bids 512-1023), fused.
    fused_attn_out<<<1024, 256, FLASH_SMEM>>>(hq, hk, hv, hctx,
                                              hw + 3 * NW, out, bo);
}